// round 17
// baseline (speedup 1.0000x reference)
#include <cuda_runtime.h>
#include <cuda_fp16.h>
#include <cstdint>

#define IN_FEATS 128
#define HIDDEN   256
#define NMAX     100000

// fp16 per-node projections: u = Hs@W1a + b1, v = Hd@W1b
__device__ __align__(16) unsigned short g_u[(size_t)NMAX * HIDDEN];
__device__ __align__(16) unsigned short g_v[(size_t)NMAX * HIDDEN];

// ---------------------------------------------------------------------------
// helpers
// ---------------------------------------------------------------------------
__device__ __forceinline__ uint32_t smem_u32(const void* p) {
    uint32_t a;
    asm("{ .reg .u64 t; cvta.to.shared.u64 t, %1; cvt.u32.u64 %0, t; }"
        : "=r"(a) : "l"(p));
    return a;
}
__device__ __forceinline__ void cp_async16(uint32_t dst, const void* src) {
    asm volatile("cp.async.cg.shared.global [%0], [%1], 16;"
                 :: "r"(dst), "l"(src));
}
__device__ __forceinline__ void cp_async16z(uint32_t dst, const void* src,
                                            int srcsz) {
    asm volatile("cp.async.cg.shared.global [%0], [%1], 16, %2;"
                 :: "r"(dst), "l"(src), "r"(srcsz));
}
__device__ __forceinline__ void cp_async_commit() {
    asm volatile("cp.async.commit_group;");
}
__device__ __forceinline__ void cp_async_wait_all() {
    asm volatile("cp.async.wait_group 0;" ::: "memory");
}
__device__ __forceinline__ void cp_async_wait2() {
    asm volatile("cp.async.wait_group 2;" ::: "memory");
}
__device__ __forceinline__ void ldsm4(uint32_t* r, uint32_t a) {
    asm volatile("ldmatrix.sync.aligned.m8n8.x4.shared.b16 {%0,%1,%2,%3}, [%4];"
                 : "=r"(r[0]), "=r"(r[1]), "=r"(r[2]), "=r"(r[3]) : "r"(a));
}
// m16n8k16 fp16 mma, fp32 accum
__device__ __forceinline__ void mma_f16(float* d, const uint32_t* a,
                                        const uint32_t* b) {
    asm volatile(
        "mma.sync.aligned.m16n8k16.row.col.f32.f16.f16.f32 "
        "{%0,%1,%2,%3}, {%4,%5,%6,%7}, {%8,%9}, {%0,%1,%2,%3};"
        : "+f"(d[0]), "+f"(d[1]), "+f"(d[2]), "+f"(d[3])
        : "r"(a[0]), "r"(a[1]), "r"(a[2]), "r"(a[3]), "r"(b[0]), "r"(b[1]));
}
__device__ __forceinline__ uint32_t pack_h2(float a, float b) {
    __half2 p = __floats2half2_rn(a, b);
    return *reinterpret_cast<uint32_t*>(&p);
}
// row-local XOR swizzle: rows 256B (128 fp16), chunk(16B) ^= (row & 7)
__device__ __forceinline__ uint32_t swz(uint32_t row, uint32_t kbyte) {
    return row * 256u + ((((kbyte >> 4) ^ (row & 7u)) << 4) | (kbyte & 15u));
}

// SMEM layout (dynamic), r11-verified: 32-row M tiles -> 2 CTAs/SM:
static constexpr int SM_B  = 0;           // 256 rows x 256B = 64KB
static constexpr int SM_A  = 65536;       // 32 rows x 256B = 8KB
static constexpr int SM_AF = 73728;       // fp32 staging 32 x 528B = 16896
static constexpr int AF_STRIDE = 528;
static constexpr int SM_TOTAL = 90624;

// issue cp.async for fp32 A tile (32 rows x 128 f32), ZFILL beyond M
__device__ __forceinline__ void load_A_async(const float* __restrict__ A,
                                             int M, int bm, uint32_t smb,
                                             int tid)
{
    #pragma unroll
    for (int i = 0; i < 4; i++) {
        const int o   = tid + i * 256;
        const int row = o >> 5;
        const int c   = o & 31;
        const float* src = A + (size_t)(bm + row) * IN_FEATS + c * 4;
        const uint32_t dst = smb + SM_AF + row * AF_STRIDE + c * 16;
        cp_async16z(dst, src, (bm + row < M) ? 16 : 0);
    }
    cp_async_commit();
}

// ---------------------------------------------------------------------------
// Persistent node GEMM (fp16): r15/r16-verified (prep_W folded in), unchanged.
// ---------------------------------------------------------------------------
__global__ __launch_bounds__(256, 2)
void node_gemm_persistent(const float* __restrict__ Hs,
                          const float* __restrict__ Hd,
                          const float* __restrict__ W1,
                          const float* __restrict__ b1,
                          int M, int nTiles)
{
    extern __shared__ char smem[];
    __shared__ float sB1[HIDDEN];
    const uint32_t smb = smem_u32(smem);

    const int tid  = threadIdx.x;
    const int wid  = tid >> 5;
    const int lane = tid & 31;

    const bool is_u = (blockIdx.x & 1) == 0;
    const int  cta  = blockIdx.x >> 1;
    const int  nCta = gridDim.x >> 1;
    const float* __restrict__ A = is_u ? Hs : Hd;
    unsigned short* __restrict__ C = is_u ? g_u : g_v;

    if (cta < nTiles) load_A_async(A, M, cta * 32, smb, tid);

    {
        const float* Wcol = W1 + (is_u ? 0 : (size_t)IN_FEATS * HIDDEN) + tid;
        #pragma unroll
        for (int c = 0; c < 16; c++) {
            uint32_t p[4];
            #pragma unroll
            for (int j = 0; j < 4; j++) {
                const float w0 = Wcol[(size_t)(c * 8 + 2 * j) * HIDDEN];
                const float w1 = Wcol[(size_t)(c * 8 + 2 * j + 1) * HIDDEN];
                p[j] = pack_h2(w0, w1);
            }
            const uint32_t off =
                (uint32_t)tid * 256u + (uint32_t)(((c ^ (tid & 7)) << 4));
            *reinterpret_cast<uint4*>(smem + SM_B + off) =
                make_uint4(p[0], p[1], p[2], p[3]);
        }
    }
    sB1[tid] = b1[tid];
    cp_async_wait_all();
    __syncthreads();

    const int nbase = wid * 32;

    const uint32_t rowA  = (uint32_t)(lane & 15);
    const uint32_t xorA  = rowA & 7u;
    const uint32_t chA0  = (uint32_t)(lane >> 4);
    const uint32_t baseA = rowA * 256u;

    const uint32_t rowB  = (uint32_t)(nbase + (lane & 7) + ((lane >> 4) << 3));
    const uint32_t xorB  = rowB & 7u;
    const uint32_t chB0  = (uint32_t)((lane >> 3) & 1);
    const uint32_t baseB = rowB * 256u;

    const int cvRow = tid >> 3;
    const int cvKq  = (tid & 7) * 16;
    const char* cvStage = smem + SM_AF + cvRow * AF_STRIDE;

    for (int t = cta; t < nTiles; t += nCta) {
        const int bm = t * 32;

        #pragma unroll
        for (int j = 0; j < 4; j++) {
            const int k = cvKq + j * 4;
            const float4 x = *reinterpret_cast<const float4*>(cvStage + k * 4);
            uint2 hv;
            hv.x = pack_h2(x.x, x.y);
            hv.y = pack_h2(x.z, x.w);
            const uint32_t o = swz((uint32_t)cvRow, (uint32_t)(k * 2));
            *reinterpret_cast<uint2*>(smem + SM_A + o) = hv;
        }
        __syncthreads();

        const int tn = t + nCta;
        if (tn < nTiles) load_A_async(A, M, tn * 32, smb, tid);

        float acc[2][4][4];
        #pragma unroll
        for (int mt = 0; mt < 2; mt++)
            #pragma unroll
            for (int nt = 0; nt < 4; nt++)
                #pragma unroll
                for (int q = 0; q < 4; q++) acc[mt][nt][q] = 0.f;

        #pragma unroll
        for (int ks = 0; ks < 8; ks++) {
            const uint32_t aAddr0 =
                smb + SM_A + baseA + (((chA0 + 2u * ks) ^ xorA) << 4);
            const uint32_t bAddr0 =
                smb + SM_B + baseB + (((chB0 + 2u * ks) ^ xorB) << 4);
            uint32_t af[2][4], bf[2][4];
            #pragma unroll
            for (int mt = 0; mt < 2; mt++)
                ldsm4(af[mt], aAddr0 + mt * 16 * 256);
            #pragma unroll
            for (int bt = 0; bt < 2; bt++)
                ldsm4(bf[bt], bAddr0 + bt * 16 * 256);
            #pragma unroll
            for (int mt = 0; mt < 2; mt++)
                #pragma unroll
                for (int bt = 0; bt < 2; bt++) {
                    mma_f16(acc[mt][2 * bt],     af[mt], &bf[bt][0]);
                    mma_f16(acc[mt][2 * bt + 1], af[mt], &bf[bt][2]);
                }
        }

        #pragma unroll
        for (int mt = 0; mt < 2; mt++) {
            const int m0 = mt * 16 + (lane >> 2);
            #pragma unroll
            for (int half = 0; half < 2; half++) {
                const int grow = bm + m0 + half * 8;
                if (grow >= M) continue;
                unsigned short* orow = C + (size_t)grow * HIDDEN;
                #pragma unroll
                for (int nt = 0; nt < 4; nt++) {
                    const int n = nbase + nt * 8 + (lane & 3) * 2;
                    float f0 = acc[mt][nt][2 * half];
                    float f1 = acc[mt][nt][2 * half + 1];
                    if (is_u) { f0 += sB1[n]; f1 += sB1[n + 1]; }
                    *reinterpret_cast<uint32_t*>(orow + n) = pack_h2(f0, f1);
                }
            }
        }

        cp_async_wait_all();
        __syncthreads();
    }
}

// ---------------------------------------------------------------------------
// Edge pass: cp.async ring depth 3, 16 edges/warp, fp16 SIMD add+relu,
// SMEM-staged batched output stores.
// Lanes 0-15 hold src indices for edges 0-15; lanes 16-31 hold dst indices.
// ---------------------------------------------------------------------------
#define EPW 16     // edges per warp
#define EDEPTH 3   // ring depth

__global__ __launch_bounds__(256)
void edge_score_kernel(const int* __restrict__ src,
                       const int* __restrict__ dst,
                       const float* __restrict__ W2,
                       const float* __restrict__ b2,
                       float* __restrict__ out,
                       int E)
{
    __shared__ float sW2[HIDDEN];
    __shared__ __align__(16) char sbuf[8][EDEPTH][2][512];
    __shared__ __align__(16) float sres[8][EPW];

    const int tid = threadIdx.x;
    sW2[tid] = W2[tid];
    __syncthreads();

    const int lane = tid & 31;
    const int warp = tid >> 5;

    const float4 wA = *reinterpret_cast<const float4*>(&sW2[lane * 8]);
    const float4 wB = *reinterpret_cast<const float4*>(&sW2[lane * 8 + 4]);
    const float w[8] = {wA.x, wA.y, wA.z, wA.w, wB.x, wB.y, wB.z, wB.w};
    const float bias = b2[0];

    const int e_base = (blockIdx.x * 8 + warp) * EPW;
    if (e_base >= E) return;

    // one index per lane: lanes 0-15 src[e_base+lane], 16-31 dst[e_base+lane-16]
    const int eIdx = min(e_base + (lane & 15), E - 1);
    const int idx = (lane < 16) ? src[eIdx] : dst[eIdx];

    const uint32_t ubuf0 = smem_u32(&sbuf[warp][0][0][0]) + lane * 16;
    const uint32_t vbuf0 = smem_u32(&sbuf[warp][0][1][0]) + lane * 16;

    // prologue: issue stages 0..1
    #pragma unroll
    for (int st = 0; st < EDEPTH - 1; st++) {
        const int s = __shfl_sync(0xFFFFFFFFu, idx, st);
        const int d = __shfl_sync(0xFFFFFFFFu, idx, 16 + st);
        cp_async16(ubuf0 + st * 1024, g_u + (size_t)s * HIDDEN + lane * 8);
        cp_async16(vbuf0 + st * 1024, g_v + (size_t)d * HIDDEN + lane * 8);
        cp_async_commit();
    }

    const __half2 zero2 = __float2half2_rn(0.f);

    #pragma unroll
    for (int i = 0; i < EPW; i++) {
        // issue stage i+2 (or empty commit to keep pending-count semantics)
        if (i + EDEPTH - 1 < EPW) {
            const int st = i + EDEPTH - 1;
            const int s = __shfl_sync(0xFFFFFFFFu, idx, st);
            const int d = __shfl_sync(0xFFFFFFFFu, idx, 16 + st);
            const int buf = st % EDEPTH;
            cp_async16(ubuf0 + buf * 1024, g_u + (size_t)s * HIDDEN + lane * 8);
            cp_async16(vbuf0 + buf * 1024, g_v + (size_t)d * HIDDEN + lane * 8);
        }
        cp_async_commit();
        cp_async_wait2();          // stage i complete

        const int buf = i % EDEPTH;
        const uint4 ur = *reinterpret_cast<const uint4*>(
            &sbuf[warp][buf][0][lane * 16]);
        const uint4 vr = *reinterpret_cast<const uint4*>(
            &sbuf[warp][buf][1][lane * 16]);
        const __half2* uh = reinterpret_cast<const __half2*>(&ur);
        const __half2* vh = reinterpret_cast<const __half2*>(&vr);

        float acc = 0.f;
        #pragma unroll
        for (int q = 0; q < 4; q++) {
            const __half2 r = __hmax2(__hadd2(uh[q], vh[q]), zero2);
            const float2 f = __half22float2(r);
            acc = fmaf(f.x, w[2 * q], acc);
            acc = fmaf(f.y, w[2 * q + 1], acc);
        }
        #pragma unroll
        for (int o = 16; o > 0; o >>= 1)
            acc += __shfl_xor_sync(0xFFFFFFFFu, acc, o);

        if (lane == 0) sres[warp][i] = acc + bias;
    }
    __syncwarp();

    // batched output: 4 lanes emit 16 floats as STG.128
    if (e_base + EPW <= E) {
        if (lane < 4)
            *reinterpret_cast<float4*>(out + e_base + lane * 4) =
                *reinterpret_cast<const float4*>(&sres[warp][lane * 4]);
    } else {
        if (lane < EPW && (e_base + lane) < E)
            out[e_base + lane] = sres[warp][lane];
    }
}

// ---------------------------------------------------------------------------
extern "C" void kernel_launch(void* const* d_in, const int* in_sizes, int n_in,
                              void* d_out, int out_size)
{
    const float* Hs = (const float*)d_in[0];
    const float* Hd = (const float*)d_in[1];
    const int*   src = (const int*)d_in[2];
    const int*   dst = (const int*)d_in[3];
    const float* W1 = (const float*)d_in[4];
    const float* b1 = (const float*)d_in[5];
    const float* W2 = (const float*)d_in[6];
    const float* b2 = (const float*)d_in[7];
    float* out = (float*)d_out;

    const int M = in_sizes[0] / IN_FEATS;
    const int E = in_sizes[2];
    const int nTiles = (M + 31) / 32;

    cudaFuncSetAttribute(node_gemm_persistent,
                         cudaFuncAttributeMaxDynamicSharedMemorySize, SM_TOTAL);

    node_gemm_persistent<<<296, 256, SM_TOTAL>>>(Hs, Hd, W1, b1, M, nTiles);

    const int nWarps = (E + EPW - 1) / EPW;
    edge_score_kernel<<<(nWarps + 7) / 8, 256>>>(src, dst, W2, b2, out, E);
}